// round 4
// baseline (speedup 1.0000x reference)
#include <cuda_runtime.h>
#include <math.h>
#include <stdint.h>

#define MAXB   64
#define MAXP   8732
#define MAXBP  (MAXB * MAXP)
#define MAXG   16
#define SLICES 8
#define CHUNKMAX 1100
#define SM_ROWS 32
#define MAXNBLK 280

// ---------------- scratch (static device globals; no allocation) ----------------
__device__ unsigned      g_negkey[MAXBP];
__device__ unsigned char g_plab[MAXBP];
__device__ unsigned long long g_slice_best[MAXB * SLICES * MAXG];
__device__ int      g_arrive[MAXB];
__device__ int      g_exit[MAXB];
__device__ float    g_part_box[MAXB * SLICES];
__device__ int      g_part_npos[MAXB * SLICES];
__device__ float    g_sm_ce[MAXB * MAXNBLK];
__device__ float    g_batch_cls[MAXB];
__device__ int      g_done;

// =====================================================================
// K1: fused matching.  grid (B, SLICES), 256 threads, all co-resident.
// Emits per-prior label byte, per-(b,slice) box-loss and npos partials.
// =====================================================================
__global__ __launch_bounds__(256, 4) void match_fused(
    const float* __restrict__ priors,
    const float* __restrict__ box_reg,
    const float* __restrict__ gt_boxes,
    const int*   __restrict__ gt_labels,
    int P, int G, int chunk)
{
    const int b = blockIdx.x, sl = blockIdx.y;
    const int S = gridDim.y;
    const int tid = threadIdx.x;
    const int NT = blockDim.x;

    __shared__ float gx0[MAXG], gy0[MAXG], gx1[MAXG], gy1[MAXG], ga[MAXG];
    __shared__ int   glab[MAXG], bp[MAXG];
    __shared__ unsigned long long red[MAXG][8];
    __shared__ float s_mval[CHUNKMAX];
    __shared__ int   s_mg[CHUNKMAX];
    __shared__ float rb[256];
    __shared__ int   rn[256];

    if (tid < G) {
        float4 gv = __ldg((const float4*)gt_boxes + b * G + tid);
        gx0[tid] = gv.x; gy0[tid] = gv.y; gx1[tid] = gv.z; gy1[tid] = gv.w;
        ga[tid]  = (gv.z - gv.x) * (gv.w - gv.y);
        glab[tid] = gt_labels[b * G + tid];
    }
    __syncthreads();

    const int p0 = sl * chunk;
    const int p1 = min(P, p0 + chunk);
    const float4* pr4 = (const float4*)priors;

    unsigned long long bestk[MAXG];
#pragma unroll
    for (int g = 0; g < MAXG; g++) bestk[g] = 0ull;

    for (int p = p0 + tid; p < p1; p += NT) {
        float4 pv = __ldg(&pr4[p]);
        float px0 = pv.x - 0.5f * pv.z, py0 = pv.y - 0.5f * pv.w;
        float px1 = pv.x + 0.5f * pv.z, py1 = pv.y + 0.5f * pv.w;
        float parea = (px1 - px0) * (py1 - py0);

        float mval = -1.0f; int mg = 0;
#pragma unroll
        for (int g = 0; g < MAXG; g++) {
            if (g >= G) break;
            float ix0 = fmaxf(gx0[g], px0), iy0 = fmaxf(gy0[g], py0);
            float ix1 = fminf(gx1[g], px1), iy1 = fminf(gy1[g], py1);
            float iw = fmaxf(ix1 - ix0, 0.0f), ih = fmaxf(iy1 - iy0, 0.0f);
            float inter = iw * ih;
            float iou = inter / (ga[g] + parea - inter);  // IEEE div (matches ref)
            if (iou > mval) { mval = iou; mg = g; }       // first-g tie-break
            unsigned long long key =
                ((unsigned long long)__float_as_uint(iou) << 32) |
                (unsigned long long)(0xFFFFFFFFu - (unsigned)p); // lower p wins
            if (key > bestk[g]) bestk[g] = key;
        }
        s_mval[p - p0] = mval;
        s_mg[p - p0]   = mg;
    }

    const int lane = tid & 31, warp = tid >> 5;
#pragma unroll
    for (int g = 0; g < MAXG; g++) {
        if (g >= G) break;
        unsigned long long k = bestk[g];
#pragma unroll
        for (int o = 16; o > 0; o >>= 1) {
            unsigned long long other = __shfl_down_sync(0xffffffffu, k, o);
            if (other > k) k = other;
        }
        if (lane == 0) red[g][warp] = k;
    }
    __syncthreads();
    if (tid < G) {
        unsigned long long k = red[tid][0];
        for (int wi = 1; wi < NT / 32; wi++)
            if (red[tid][wi] > k) k = red[tid][wi];
        g_slice_best[(b * S + sl) * MAXG + tid] = k;
    }

    // ---- grid handshake (all 512 blocks co-resident) ----
    __threadfence();
    __syncthreads();
    if (tid == 0) {
        atomicAdd(&g_arrive[b], 1);
        while (atomicAdd(&g_arrive[b], 0) < S) { }
    }
    __syncthreads();
    __threadfence();

    if (tid < G) {
        unsigned long long k = 0ull;
        for (int s2 = 0; s2 < S; s2++) {
            unsigned long long v =
                *(volatile unsigned long long*)&g_slice_best[(b * S + s2) * MAXG + tid];
            if (v > k) k = v;
        }
        bp[tid] = (int)(0xFFFFFFFFu - (unsigned)(k & 0xFFFFFFFFull));
    }
    __syncthreads();

    // inject overrides into shared (ascending g: last-GT-wins, matches .set)
    if (tid == 0) {
        for (int g = 0; g < G; g++) {
            int pp = bp[g];
            if (pp >= p0 && pp < p1) { s_mval[pp - p0] = 2.0f; s_mg[pp - p0] = g; }
        }
    }
    __syncthreads();

    // ---- phase 2: labels, box smooth-L1 (gt_labels >= 1 so pos <=> mval>=0.5)
    float box_sum = 0.0f;
    int npos = 0;
    for (int p = p0 + tid; p < p1; p += NT) {
        float mval = s_mval[p - p0];
        const int idx = b * P + p;
        if (mval >= 0.5f) {
            const int mg = s_mg[p - p0];
            const int lab = glab[mg];
            g_plab[idx] = (unsigned char)lab;
            npos++;
            float4 pv = __ldg(&pr4[p]);
            float bx0 = gx0[mg], by0 = gy0[mg], bx1 = gx1[mg], by1 = gy1[mg];
            float t0 = ((bx0 + bx1) * 0.5f - pv.x) / (0.1f * pv.z);
            float t1 = ((by0 + by1) * 0.5f - pv.y) / (0.1f * pv.w);
            float t2 = logf((bx1 - bx0) / pv.z) / 0.2f;
            float t3 = logf((by1 - by0) / pv.w) / 0.2f;
            float4 br = __ldg((const float4*)box_reg + idx);
            float d0 = fabsf(br.x - t0), d1 = fabsf(br.y - t1);
            float d2 = fabsf(br.z - t2), d3 = fabsf(br.w - t3);
            box_sum += (d0 < 1.0f) ? 0.5f * d0 * d0 : d0 - 0.5f;
            box_sum += (d1 < 1.0f) ? 0.5f * d1 * d1 : d1 - 0.5f;
            box_sum += (d2 < 1.0f) ? 0.5f * d2 * d2 : d2 - 0.5f;
            box_sum += (d3 < 1.0f) ? 0.5f * d3 * d3 : d3 - 0.5f;
        } else {
            g_plab[idx] = 0;
        }
    }

    rb[tid] = box_sum; rn[tid] = npos;
    __syncthreads();
    for (int st = NT / 2; st > 0; st >>= 1) {
        if (tid < st) { rb[tid] += rb[tid + st]; rn[tid] += rn[tid + st]; }
        __syncthreads();
    }
    if (tid == 0) {
        int pi = b * S + sl;
        g_part_box[pi]  = rb[0];
        g_part_npos[pi] = rn[0];
        int v = atomicAdd(&g_exit[b], 1);          // self-reset counters
        if (v == S - 1) { g_exit[b] = 0; g_arrive[b] = 0; }
    }
}

// =====================================================================
// K2: log-sum-exp rows (float4-staged through shared).  Reads the label
// byte; emits negkey (0 for positives) and per-block positive-CE partial.
// =====================================================================
__global__ __launch_bounds__(256) void softmax_kernel(
    const float* __restrict__ logits, int P, int C, int nblk)
{
    __shared__ float s[SM_ROWS * 96];
    __shared__ float wce[8];

    const int b  = blockIdx.y;
    const int r0 = blockIdx.x * SM_ROWS;
    const int R  = min(SM_ROWS, P - r0);
    const int tid = threadIdx.x;

    const float* base = logits + ((size_t)b * P + r0) * C;
    const int nflt = R * C;
    const int nvec = nflt >> 2;
    const float4* b4 = (const float4*)base;
    for (int i = tid; i < nvec; i += 256) {
        float4 v = __ldg(&b4[i]);
        s[i * 4 + 0] = v.x; s[i * 4 + 1] = v.y;
        s[i * 4 + 2] = v.z; s[i * 4 + 3] = v.w;
    }
    for (int i = (nvec << 2) + tid; i < nflt; i += 256) s[i] = __ldg(&base[i]);
    __syncthreads();

    const int warp = tid >> 5, lane = tid & 31;
    float ce_local = 0.0f;
#pragma unroll
    for (int j = 0; j < SM_ROWS / 8; j++) {
        const int row = warp + j * 8;
        if (row >= R) break;
        const float* rp = s + row * C;
        float x0 = (lane      < C) ? rp[lane]      : 0.0f;
        float x1 = (lane + 32 < C) ? rp[lane + 32] : 0.0f;
        float x2 = (lane + 64 < C) ? rp[lane + 64] : 0.0f;
        float sum = 0.0f;
        if (lane      < C) sum += __expf(x0);
        if (lane + 32 < C) sum += __expf(x1);
        if (lane + 64 < C) sum += __expf(x2);
#pragma unroll
        for (int o = 16; o > 0; o >>= 1) sum += __shfl_xor_sync(0xffffffffu, sum, o);
        if (lane == 0) {
            float lse = __logf(sum);
            int idx = b * P + r0 + row;
            int lab = (int)g_plab[idx];
            if (lab > 0) {
                g_negkey[idx] = 0u;
                ce_local += lse - rp[lab];
            } else {
                g_negkey[idx] = __float_as_uint(fmaxf(lse - rp[0], 0.0f));
            }
        }
    }
    if (lane == 0) wce[warp] = ce_local;
    __syncthreads();
    if (tid == 0) {
        float c = 0.0f;
#pragma unroll
        for (int w2 = 0; w2 < 8; w2++) c += wce[w2];
        g_sm_ce[b * nblk + blockIdx.x] = c;
    }
}

// =====================================================================
// K3: per-batch exact top-k sum (smem-staged, 3-pass histogram select)
// + fused finalize in the last-finishing block.
// =====================================================================
__global__ __launch_bounds__(512) void topk_kernel(
    float* __restrict__ out, int P, int B, int S, int nblk)
{
    const int b = blockIdx.x;
    const int tid = threadIdx.x;
    const int NT = 512;

    __shared__ unsigned sk[MAXP];
    __shared__ int   hist[4096];
    __shared__ int   suf[256];
    __shared__ float rs[512];
    __shared__ int   rn2[512];
    __shared__ int   f_bucket, f_above, sh_k;
    __shared__ float sh_ce;
    __shared__ int   sh_last;

    // stage keys (uint4: P and b*P both 16B-aligned multiples of 4 elems)
    {
        const uint4* nk4 = (const uint4*)(g_negkey + b * P);
        const int nv = P >> 2;
        for (int i = tid; i < nv; i += NT) {
            uint4 v = __ldg(&nk4[i]);
            sk[i * 4 + 0] = v.x; sk[i * 4 + 1] = v.y;
            sk[i * 4 + 2] = v.z; sk[i * 4 + 3] = v.w;
        }
        for (int i = (nv << 2) + tid; i < P; i += NT) sk[i] = g_negkey[b * P + i];
    }

    // positive-CE partials (273 values) and npos (8 values)
    float ce = 0.0f;
    for (int i = tid; i < nblk; i += NT) ce += g_sm_ce[b * nblk + i];
    int np = 0;
    if (tid < S) np = g_part_npos[b * S + tid];
    rs[tid] = ce; rn2[tid] = np;
    __syncthreads();
    for (int st = NT / 2; st > 0; st >>= 1) {
        if (tid < st) { rs[tid] += rs[tid + st]; rn2[tid] += rn2[tid + st]; }
        __syncthreads();
    }
    if (tid == 0) {
        int k = rn2[0] * 3; if (k > P) k = P;
        sh_k = k; sh_ce = rs[0];
    }
    __syncthreads();
    int k = sh_k;

    float cls = sh_ce;
    if (k > 0) {
        unsigned prefix = 0;
        const int shifts[3] = {20, 8, 0};
        const int bitsA[3]  = {12, 12, 8};
#pragma unroll
        for (int ps = 0; ps < 3; ps++) {
            const int shift = shifts[ps];
            const int nbits = bitsA[ps];
            const int nb = 1 << nbits;
            const unsigned himask = (unsigned)(~((1ull << (shift + nbits)) - 1ull));

            for (int i = tid; i < nb; i += NT) hist[i] = 0;
            __syncthreads();

            for (int p = tid; p < P; p += NT) {
                unsigned key = sk[p];
                if ((key & himask) == prefix)
                    atomicAdd(&hist[(key >> shift) & (nb - 1)], 1);
            }
            __syncthreads();

            const int cw = nb >> 8;
            int cs = 0;
            if (tid < 256) {
                for (int i = 0; i < cw; i++) cs += hist[tid * cw + i];
                suf[tid] = cs;
            }
            __syncthreads();
            for (int off = 1; off < 256; off <<= 1) {
                int v = 0;
                if (tid < 256) v = (tid + off < 256) ? suf[tid + off] : 0;
                __syncthreads();
                if (tid < 256) suf[tid] += v;
                __syncthreads();
            }
            if (tid < 256) {
                int running = suf[tid] - cs;             // strictly above my chunk
                for (int i = cw - 1; i >= 0; i--) {
                    int c = hist[tid * cw + i];
                    if (c > 0 && running < k && running + c >= k) {
                        f_bucket = tid * cw + i;         // unique writer
                        f_above  = running;
                    }
                    running += c;
                }
            }
            __syncthreads();
            prefix |= ((unsigned)f_bucket) << shift;
            k -= f_above;
            __syncthreads();
        }

        float ss = 0.0f;
        for (int p = tid; p < P; p += NT) {
            unsigned key = sk[p];
            if (key > prefix) ss += __uint_as_float(key);
        }
        rs[tid] = ss;
        __syncthreads();
        for (int st = NT / 2; st > 0; st >>= 1) {
            if (tid < st) rs[tid] += rs[tid + st];
            __syncthreads();
        }
        cls += rs[0] + (float)k * __uint_as_float(prefix);
    }

    if (tid == 0) {
        g_batch_cls[b] = cls;
        __threadfence();
        int v = atomicAdd(&g_done, 1);
        sh_last = (v == B - 1) ? 1 : 0;
    }
    __syncthreads();

    // ---- last block: finalize ----
    if (sh_last) {
        float box = 0.0f, ctot = 0.0f; int npos = 0;
        for (int i = tid; i < B * S; i += NT) {
            box  += g_part_box[i];
            npos += g_part_npos[i];
        }
        for (int i = tid; i < B; i += NT)
            ctot += *(volatile float*)&g_batch_cls[i];
        rs[tid] = box; rn2[tid] = npos;
        __syncthreads();
        for (int st = NT / 2; st > 0; st >>= 1) {
            if (tid < st) { rs[tid] += rs[tid + st]; rn2[tid] += rn2[tid + st]; }
            __syncthreads();
        }
        __shared__ float sc2[512];
        sc2[tid] = ctot;
        __syncthreads();
        for (int st = NT / 2; st > 0; st >>= 1) {
            if (tid < st) sc2[tid] += sc2[tid + st];
            __syncthreads();
        }
        if (tid == 0) {
            float inv = 1.0f / (float)rn2[0];
            out[0] = rs[0] * inv;
            out[1] = sc2[0] * inv;
            g_done = 0;                              // self-reset for replay
        }
    }
}

// =====================================================================
extern "C" void kernel_launch(void* const* d_in, const int* in_sizes, int n_in,
                              void* d_out, int out_size)
{
    const float* priors = (const float*)d_in[0];
    const float* logits = (const float*)d_in[1];
    const float* boxreg = (const float*)d_in[2];
    const float* gtb    = (const float*)d_in[3];
    const int*   gtl    = (const int*)d_in[4];

    const int P = in_sizes[0] / 4;
    const int B = in_sizes[2] / (4 * P);
    const int C = in_sizes[1] / (B * P);
    const int G = in_sizes[4] / B;
    const int chunk = (P + SLICES - 1) / SLICES;
    const int nblk  = (P + SM_ROWS - 1) / SM_ROWS;

    dim3 gm(B, SLICES);
    match_fused<<<gm, 256>>>(priors, boxreg, gtb, gtl, P, G, chunk);

    dim3 gs(nblk, B);
    softmax_kernel<<<gs, 256>>>(logits, P, C, nblk);

    topk_kernel<<<B, 512>>>((float*)d_out, P, B, SLICES, nblk);
}

// round 5
// speedup vs baseline: 1.0648x; 1.0648x over previous
#include <cuda_runtime.h>
#include <math.h>
#include <stdint.h>

#define MAXB    64
#define MAXP    8732
#define MAXBP   (MAXB * MAXP)
#define MAXG    16
#define SLICES  8
#define SM_ROWS 64
#define MAXNBLK 140

// ---------------- scratch (static device globals; zero-initialized) ----------------
__device__ unsigned      g_negkey[MAXBP];
__device__ unsigned char g_mbyte[MAXBP];     // bit7 = pos, bits0-3 = argmax g
__device__ unsigned long long g_bestkey[MAXB * MAXG];   // zero-init; reset by topk
__device__ float g_part_ce[MAXB * MAXNBLK];
__device__ float g_part_box[MAXB * MAXNBLK];
__device__ int   g_part_np[MAXB * MAXNBLK];
__device__ float g_batch_cls[MAXB];
__device__ float g_batch_box[MAXB];
__device__ int   g_batch_np[MAXB];
__device__ int   g_done;

// =====================================================================
// K1: IoU matching sweep.  grid (B, SLICES), 256 threads.
// Writes per-prior byte (argmax g + pos flag) and per-GT best-prior key
// via u64 atomicMax (order-independent => deterministic).
// =====================================================================
__global__ __launch_bounds__(256) void match_part(
    const float* __restrict__ priors,
    const float* __restrict__ gt_boxes,
    int P, int G, int chunk)
{
    const int b = blockIdx.x, sl = blockIdx.y;
    const int tid = threadIdx.x;
    const int NT = 256;

    __shared__ float gx0[MAXG], gy0[MAXG], gx1[MAXG], gy1[MAXG], ga[MAXG];
    __shared__ unsigned long long red[MAXG][8];

    if (tid < G) {
        float4 gv = __ldg((const float4*)gt_boxes + b * G + tid);
        gx0[tid] = gv.x; gy0[tid] = gv.y; gx1[tid] = gv.z; gy1[tid] = gv.w;
        ga[tid]  = (gv.z - gv.x) * (gv.w - gv.y);
    }
    __syncthreads();

    const int p0 = sl * chunk;
    const int p1 = min(P, p0 + chunk);
    const float4* pr4 = (const float4*)priors;

    unsigned long long bestk[MAXG];
#pragma unroll
    for (int g = 0; g < MAXG; g++) bestk[g] = 0ull;

    for (int p = p0 + tid; p < p1; p += NT) {
        float4 pv = __ldg(&pr4[p]);
        float px0 = pv.x - 0.5f * pv.z, py0 = pv.y - 0.5f * pv.w;
        float px1 = pv.x + 0.5f * pv.z, py1 = pv.y + 0.5f * pv.w;
        float parea = (px1 - px0) * (py1 - py0);

        float mval = -1.0f; int mg = 0;
#pragma unroll
        for (int g = 0; g < MAXG; g++) {
            if (g >= G) break;
            float ix0 = fmaxf(gx0[g], px0), iy0 = fmaxf(gy0[g], py0);
            float ix1 = fminf(gx1[g], px1), iy1 = fminf(gy1[g], py1);
            float iw = fmaxf(ix1 - ix0, 0.0f), ih = fmaxf(iy1 - iy0, 0.0f);
            float inter = iw * ih;
            float iou = inter / (ga[g] + parea - inter);  // IEEE div (matches ref)
            if (iou > mval) { mval = iou; mg = g; }       // first-g tie-break
            unsigned long long key =
                ((unsigned long long)__float_as_uint(iou) << 32) |
                (unsigned long long)(0xFFFFFFFFu - (unsigned)p); // lower p wins
            if (key > bestk[g]) bestk[g] = key;
        }
        g_mbyte[b * P + p] =
            (unsigned char)(mg | ((mval >= 0.5f) ? 0x80 : 0));
    }

    const int lane = tid & 31, warp = tid >> 5;
#pragma unroll
    for (int g = 0; g < MAXG; g++) {
        if (g >= G) break;
        unsigned long long k = bestk[g];
#pragma unroll
        for (int o = 16; o > 0; o >>= 1) {
            unsigned long long other = __shfl_down_sync(0xffffffffu, k, o);
            if (other > k) k = other;
        }
        if (lane == 0) red[g][warp] = k;
    }
    __syncthreads();
    if (tid < G) {
        unsigned long long k = red[tid][0];
#pragma unroll
        for (int wi = 1; wi < 8; wi++)
            if (red[tid][wi] > k) k = red[tid][wi];
        atomicMax(&g_bestkey[b * MAXG + tid], k);
    }
}

// =====================================================================
// K2: softmax + apply.  grid (nblk, B), 256 threads, SM_ROWS=64 rows.
// Stages logits via float4, resolves overrides for its rows, computes
// lse, negkey, positive CE, box smooth-L1, npos partials.
// =====================================================================
__global__ __launch_bounds__(256) void softmax_apply(
    const float* __restrict__ logits,
    const float* __restrict__ priors,
    const float* __restrict__ box_reg,
    const float* __restrict__ gt_boxes,
    const int*   __restrict__ gt_labels,
    int P, int C, int G, int nblk)
{
    __shared__ float s[SM_ROWS * 81];
    __shared__ float gx0[MAXG], gy0[MAXG], gx1[MAXG], gy1[MAXG];
    __shared__ int   glab[MAXG], bp[MAXG];
    __shared__ int   s_lab[SM_ROWS];
    __shared__ float s_box[SM_ROWS];
    __shared__ float wce[8];

    const int b  = blockIdx.y;
    const int r0 = blockIdx.x * SM_ROWS;
    const int R  = min(SM_ROWS, P - r0);
    const int tid = threadIdx.x;

    // early independent loads
    unsigned mbyte = 0;
    if (tid < R) mbyte = g_mbyte[b * P + r0 + tid];
    if (tid < G) {
        float4 gv = __ldg((const float4*)gt_boxes + b * G + tid);
        gx0[tid] = gv.x; gy0[tid] = gv.y; gx1[tid] = gv.z; gy1[tid] = gv.w;
        glab[tid] = gt_labels[b * G + tid];
        bp[tid] = (int)(0xFFFFFFFFu -
                        (unsigned)(g_bestkey[b * MAXG + tid] & 0xFFFFFFFFull));
    }

    // stage R*C floats (base 16B aligned, nflt % 4 == 0 for these shapes)
    const float* base = logits + ((size_t)b * P + r0) * C;
    const int nflt = R * C;
    const int nvec = nflt >> 2;
    const float4* b4 = (const float4*)base;
    for (int i = tid; i < nvec; i += 256) {
        float4 v = __ldg(&b4[i]);
        s[i * 4 + 0] = v.x; s[i * 4 + 1] = v.y;
        s[i * 4 + 2] = v.z; s[i * 4 + 3] = v.w;
    }
    for (int i = (nvec << 2) + tid; i < nflt; i += 256) s[i] = __ldg(&base[i]);
    __syncthreads();

    // apply pre-pass: one thread per row
    if (tid < R) {
        const int p = r0 + tid;
        int mg  = (int)(mbyte & 15);
        int pos = (int)(mbyte >> 7);
#pragma unroll
        for (int g = 0; g < MAXG; g++) {        // ascending: last-GT-wins
            if (g >= G) break;
            if (bp[g] == p) { mg = g; pos = 1; }
        }
        float boxv = 0.0f;
        int lab = 0;
        if (pos) {
            lab = glab[mg];
            float4 pv = __ldg((const float4*)priors + p);
            float bx0 = gx0[mg], by0 = gy0[mg], bx1 = gx1[mg], by1 = gy1[mg];
            float t0 = ((bx0 + bx1) * 0.5f - pv.x) / (0.1f * pv.z);
            float t1 = ((by0 + by1) * 0.5f - pv.y) / (0.1f * pv.w);
            float t2 = logf((bx1 - bx0) / pv.z) / 0.2f;
            float t3 = logf((by1 - by0) / pv.w) / 0.2f;
            float4 br = __ldg((const float4*)box_reg + (b * P + p));
            float d0 = fabsf(br.x - t0), d1 = fabsf(br.y - t1);
            float d2 = fabsf(br.z - t2), d3 = fabsf(br.w - t3);
            boxv  = (d0 < 1.0f) ? 0.5f * d0 * d0 : d0 - 0.5f;
            boxv += (d1 < 1.0f) ? 0.5f * d1 * d1 : d1 - 0.5f;
            boxv += (d2 < 1.0f) ? 0.5f * d2 * d2 : d2 - 0.5f;
            boxv += (d3 < 1.0f) ? 0.5f * d3 * d3 : d3 - 0.5f;
        }
        s_lab[tid] = lab;
        s_box[tid] = boxv;
    }
    __syncthreads();

    // per-row lse / negkey / positive-CE  (8 warps x 8 rows)
    const int warp = tid >> 5, lane = tid & 31;
    float ce_local = 0.0f;
#pragma unroll
    for (int j = 0; j < SM_ROWS / 8; j++) {
        const int row = warp + j * 8;
        if (row >= R) break;
        const float* rp = s + row * 81;
        float sum = 0.0f;
        if (lane      < C) sum += __expf(rp[lane]);
        if (lane + 32 < C) sum += __expf(rp[lane + 32]);
        if (lane + 64 < C) sum += __expf(rp[lane + 64]);
#pragma unroll
        for (int o = 16; o > 0; o >>= 1) sum += __shfl_xor_sync(0xffffffffu, sum, o);
        if (lane == 0) {
            float lse = __logf(sum);
            int idx = b * P + r0 + row;
            int lab = s_lab[row];
            if (lab > 0) {
                g_negkey[idx] = 0u;
                ce_local += lse - rp[lab];
            } else {
                g_negkey[idx] = __float_as_uint(fmaxf(lse - rp[0], 0.0f));
            }
        }
    }
    if (lane == 0) wce[warp] = ce_local;
    __syncthreads();

    // block partials: ce (8 values), box + npos (R values) via warp 0
    if (warp == 0) {
        float boxv = 0.0f; int np = 0;
        if (lane < R)      { boxv += s_box[lane];      np += (s_lab[lane] > 0); }
        if (lane + 32 < R) { boxv += s_box[lane + 32]; np += (s_lab[lane + 32] > 0); }
#pragma unroll
        for (int o = 16; o > 0; o >>= 1) {
            boxv += __shfl_down_sync(0xffffffffu, boxv, o);
            np   += __shfl_down_sync(0xffffffffu, np, o);
        }
        if (lane == 0) {
            float c = 0.0f;
#pragma unroll
            for (int w2 = 0; w2 < 8; w2++) c += wce[w2];
            const int pi = b * nblk + blockIdx.x;
            g_part_ce[pi]  = c;
            g_part_box[pi] = boxv;
            g_part_np[pi]  = np;
        }
    }
}

// =====================================================================
// K3: per-batch exact top-k sum (smem-staged, 3-pass histogram select)
// + bestkey reset + fused finalize in the last-finishing block.
// =====================================================================
__global__ __launch_bounds__(512) void topk_kernel(
    float* __restrict__ out, int P, int B, int G, int nblk)
{
    const int b = blockIdx.x;
    const int tid = threadIdx.x;
    const int NT = 512;

    __shared__ unsigned sk[MAXP];
    __shared__ int   hist[4096];
    __shared__ int   suf[256];
    __shared__ float rs[512];
    __shared__ int   rn2[512];
    __shared__ float rbx[512];
    __shared__ int   f_bucket, f_above, sh_k;
    __shared__ float sh_ce;
    __shared__ int   sh_last;

    // stage keys
    {
        const uint4* nk4 = (const uint4*)(g_negkey + b * P);
        const int nv = P >> 2;
        for (int i = tid; i < nv; i += NT) {
            uint4 v = __ldg(&nk4[i]);
            sk[i * 4 + 0] = v.x; sk[i * 4 + 1] = v.y;
            sk[i * 4 + 2] = v.z; sk[i * 4 + 3] = v.w;
        }
        for (int i = (nv << 2) + tid; i < P; i += NT) sk[i] = g_negkey[b * P + i];
    }

    // partials
    float ce = 0.0f, bx = 0.0f; int np = 0;
    for (int i = tid; i < nblk; i += NT) {
        ce += g_part_ce[b * nblk + i];
        bx += g_part_box[b * nblk + i];
        np += g_part_np[b * nblk + i];
    }
    rs[tid] = ce; rbx[tid] = bx; rn2[tid] = np;
    __syncthreads();
    for (int st = NT / 2; st > 0; st >>= 1) {
        if (tid < st) { rs[tid] += rs[tid + st]; rbx[tid] += rbx[tid + st]; rn2[tid] += rn2[tid + st]; }
        __syncthreads();
    }
    if (tid == 0) {
        int k = rn2[0] * 3; if (k > P) k = P;
        sh_k = k; sh_ce = rs[0];
        g_batch_box[b] = rbx[0];
        g_batch_np[b]  = rn2[0];
    }
    // reset bestkeys for next graph replay (after softmax consumed them)
    if (tid < G) g_bestkey[b * MAXG + tid] = 0ull;
    __syncthreads();
    int k = sh_k;

    float cls = sh_ce;
    if (k > 0) {
        unsigned prefix = 0;
        const int shifts[3] = {20, 8, 0};
        const int bitsA[3]  = {12, 12, 8};
#pragma unroll
        for (int ps = 0; ps < 3; ps++) {
            const int shift = shifts[ps];
            const int nbits = bitsA[ps];
            const int nb = 1 << nbits;
            const unsigned himask = (unsigned)(~((1ull << (shift + nbits)) - 1ull));

            for (int i = tid; i < nb; i += NT) hist[i] = 0;
            __syncthreads();

            for (int p = tid; p < P; p += NT) {
                unsigned key = sk[p];
                if ((key & himask) == prefix)
                    atomicAdd(&hist[(key >> shift) & (nb - 1)], 1);
            }
            __syncthreads();

            const int cw = nb >> 8;
            int cs = 0;
            if (tid < 256) {
                for (int i = 0; i < cw; i++) cs += hist[tid * cw + i];
                suf[tid] = cs;
            }
            __syncthreads();
            for (int off = 1; off < 256; off <<= 1) {
                int v = 0;
                if (tid < 256) v = (tid + off < 256) ? suf[tid + off] : 0;
                __syncthreads();
                if (tid < 256) suf[tid] += v;
                __syncthreads();
            }
            if (tid < 256) {
                int running = suf[tid] - cs;
                for (int i = cw - 1; i >= 0; i--) {
                    int c = hist[tid * cw + i];
                    if (c > 0 && running < k && running + c >= k) {
                        f_bucket = tid * cw + i;
                        f_above  = running;
                    }
                    running += c;
                }
            }
            __syncthreads();
            prefix |= ((unsigned)f_bucket) << shift;
            k -= f_above;
            __syncthreads();
        }

        float ss = 0.0f;
        for (int p = tid; p < P; p += NT) {
            unsigned key = sk[p];
            if (key > prefix) ss += __uint_as_float(key);
        }
        rs[tid] = ss;
        __syncthreads();
        for (int st = NT / 2; st > 0; st >>= 1) {
            if (tid < st) rs[tid] += rs[tid + st];
            __syncthreads();
        }
        cls += rs[0] + (float)k * __uint_as_float(prefix);
    }

    if (tid == 0) {
        g_batch_cls[b] = cls;
        __threadfence();
        int v = atomicAdd(&g_done, 1);
        sh_last = (v == B - 1) ? 1 : 0;
    }
    __syncthreads();

    // last block: finalize
    if (sh_last) {
        float box = 0.0f, ctot = 0.0f; int npos = 0;
        for (int i = tid; i < B; i += NT) {
            box  += *(volatile float*)&g_batch_box[i];
            ctot += *(volatile float*)&g_batch_cls[i];
            npos += *(volatile int*)&g_batch_np[i];
        }
        rs[tid] = ctot; rbx[tid] = box; rn2[tid] = npos;
        __syncthreads();
        for (int st = NT / 2; st > 0; st >>= 1) {
            if (tid < st) { rs[tid] += rs[tid + st]; rbx[tid] += rbx[tid + st]; rn2[tid] += rn2[tid + st]; }
            __syncthreads();
        }
        if (tid == 0) {
            float inv = 1.0f / (float)rn2[0];
            out[0] = rbx[0] * inv;
            out[1] = rs[0] * inv;
            g_done = 0;                       // self-reset for replay
        }
    }
}

// =====================================================================
extern "C" void kernel_launch(void* const* d_in, const int* in_sizes, int n_in,
                              void* d_out, int out_size)
{
    const float* priors = (const float*)d_in[0];
    const float* logits = (const float*)d_in[1];
    const float* boxreg = (const float*)d_in[2];
    const float* gtb    = (const float*)d_in[3];
    const int*   gtl    = (const int*)d_in[4];

    const int P = in_sizes[0] / 4;
    const int B = in_sizes[2] / (4 * P);
    const int C = in_sizes[1] / (B * P);
    const int G = in_sizes[4] / B;
    const int chunk = (P + SLICES - 1) / SLICES;
    const int nblk  = (P + SM_ROWS - 1) / SM_ROWS;

    dim3 gm(B, SLICES);
    match_part<<<gm, 256>>>(priors, gtb, P, G, chunk);

    dim3 gs(nblk, B);
    softmax_apply<<<gs, 256>>>(logits, priors, boxreg, gtb, gtl, P, C, G, nblk);

    topk_kernel<<<B, 512>>>((float*)d_out, P, B, G, nblk);
}

// round 6
// speedup vs baseline: 1.1268x; 1.0582x over previous
#include <cuda_runtime.h>
#include <math.h>
#include <stdint.h>

#define MAXB    64
#define MAXP    8732
#define MAXBP   (MAXB * MAXP)
#define MAXG    16
#define TILE    256
#define SM_ROWS 64

// ---------------- scratch (static device globals; zero-initialized) -------------
__device__ unsigned      g_negkey[MAXBP];
__device__ unsigned char g_mbyte[MAXBP];                 // bit7 = pos, bits0-3 = argmax g
__device__ unsigned long long g_bestkey[MAXB * MAXG];    // zero-init; reset by K2
__device__ float g_batch_cls[MAXB];
__device__ float g_batch_box[MAXB];
__device__ int   g_batch_np[MAXB];
__device__ int   g_done;

// =====================================================================
// K1: heterogeneous kernel.  blocks [0, nMatch) do IoU matching;
// blocks [nMatch, nMatch + B*nblk) do log-sum-exp rows.
// The two roles are data-independent and overlap on the chip
// (match = ALU/issue-bound, softmax = DRAM/MUFU-bound).
// =====================================================================
__global__ __launch_bounds__(256) void fused_ms(
    const float* __restrict__ logits,
    const float* __restrict__ priors,
    const float* __restrict__ gt_boxes,
    int P, int C, int G, int nMatch, int nTiles, int nblk)
{
    __shared__ float sbuf[SM_ROWS * 81];          // softmax stage / match iou tile
    __shared__ float gx0[MAXG], gy0[MAXG], gx1[MAXG], gy1[MAXG], ga[MAXG];

    const int tid = threadIdx.x;

    if (blockIdx.x < nMatch) {
        // ---------------- match role: 256 priors per block ----------------
        const int b = blockIdx.x / nTiles;
        const int t = blockIdx.x % nTiles;
        unsigned* siou = (unsigned*)sbuf;         // [16][TILE] iou bits

        if (tid < G) {
            float4 gv = __ldg((const float4*)gt_boxes + b * G + tid);
            gx0[tid] = gv.x; gy0[tid] = gv.y; gx1[tid] = gv.z; gy1[tid] = gv.w;
            ga[tid]  = (gv.z - gv.x) * (gv.w - gv.y);
        }
        __syncthreads();

        const int p0 = t * TILE;
        const int p  = p0 + tid;

        if (p < P) {
            float4 pv = __ldg((const float4*)priors + p);
            float px0 = pv.x - 0.5f * pv.z, py0 = pv.y - 0.5f * pv.w;
            float px1 = pv.x + 0.5f * pv.z, py1 = pv.y + 0.5f * pv.w;
            float parea = (px1 - px0) * (py1 - py0);

            float mval = -1.0f; int mg = 0;
#pragma unroll
            for (int g = 0; g < MAXG; g++) {
                if (g >= G) break;
                float ix0 = fmaxf(gx0[g], px0), iy0 = fmaxf(gy0[g], py0);
                float ix1 = fminf(gx1[g], px1), iy1 = fminf(gy1[g], py1);
                float iw = fmaxf(ix1 - ix0, 0.0f), ih = fmaxf(iy1 - iy0, 0.0f);
                float inter = iw * ih;
                float iou = inter / (ga[g] + parea - inter); // IEEE div (matches ref)
                if (iou > mval) { mval = iou; mg = g; }      // first-g tie-break
                siou[g * TILE + tid] = __float_as_uint(iou); // iou>=0 => bits ordered
            }
            g_mbyte[b * P + p] =
                (unsigned char)(mg | ((mval >= 0.5f) ? 0x80 : 0));
        } else {
#pragma unroll
            for (int g = 0; g < MAXG; g++) {
                if (g >= G) break;
                siou[g * TILE + tid] = 0u;  // invalid: bits 0 at largest p -> never wins
            }
        }
        __syncthreads();

        // per-GT best prior in this tile: warp w handles g = w, w+8
        const int warp = tid >> 5, lane = tid & 31;
#pragma unroll
        for (int gg = warp; gg < MAXG; gg += 8) {
            if (gg >= G) break;
            unsigned long long best = 0ull;
#pragma unroll
            for (int i = 0; i < TILE / 32; i++) {
                const int c = lane + 32 * i;                 // conflict-free stride
                unsigned bits = siou[gg * TILE + c];
                unsigned long long key =
                    ((unsigned long long)bits << 32) |
                    (unsigned long long)(0xFFFFFFFFu - (unsigned)(p0 + c));
                if (key > best) best = key;                  // lower p wins ties
            }
#pragma unroll
            for (int o = 16; o > 0; o >>= 1) {
                unsigned long long other = __shfl_down_sync(0xffffffffu, best, o);
                if (other > best) best = other;
            }
            if (lane == 0) atomicMax(&g_bestkey[b * MAXG + gg], best);
        }
    } else {
        // ---------------- softmax role: 64 rows per block ----------------
        const int r  = blockIdx.x - nMatch;
        const int b  = r / nblk;
        const int bx = r % nblk;
        const int r0 = bx * SM_ROWS;
        const int R  = min(SM_ROWS, P - r0);

        const float* base = logits + ((size_t)b * P + r0) * C;
        const int nflt = R * C;
        const int nvec = nflt >> 2;
        const float4* b4 = (const float4*)base;
        for (int i = tid; i < nvec; i += 256) {
            float4 v = __ldg(&b4[i]);
            sbuf[i * 4 + 0] = v.x; sbuf[i * 4 + 1] = v.y;
            sbuf[i * 4 + 2] = v.z; sbuf[i * 4 + 3] = v.w;
        }
        for (int i = (nvec << 2) + tid; i < nflt; i += 256) sbuf[i] = __ldg(&base[i]);
        __syncthreads();

        const int warp = tid >> 5, lane = tid & 31;
#pragma unroll
        for (int j = 0; j < SM_ROWS / 8; j++) {
            const int row = warp + j * 8;
            if (row >= R) break;
            const float* rp = sbuf + row * 81;
            float sum = 0.0f;
            if (lane      < C) sum += __expf(rp[lane]);
            if (lane + 32 < C) sum += __expf(rp[lane + 32]);
            if (lane + 64 < C) sum += __expf(rp[lane + 64]);
#pragma unroll
            for (int o = 16; o > 0; o >>= 1)
                sum += __shfl_xor_sync(0xffffffffu, sum, o);
            if (lane == 0) {
                float lse = __logf(sum);
                g_negkey[b * P + r0 + row] =
                    __float_as_uint(fmaxf(lse - rp[0], 0.0f));   // bg_loss >= 0
            }
        }
    }
}

// =====================================================================
// K2: per-batch apply + exact top-k + finalize.  One block per batch.
// =====================================================================
__global__ __launch_bounds__(512) void apply_topk(
    float* __restrict__ out,
    const float* __restrict__ logits,
    const float* __restrict__ priors,
    const float* __restrict__ box_reg,
    const float* __restrict__ gt_boxes,
    const int*   __restrict__ gt_labels,
    int P, int C, int G, int B)
{
    const int b = blockIdx.x;
    const int tid = threadIdx.x;
    const int NT = 512;

    __shared__ unsigned sk[MAXP];                 // 34.9 KB keys
    __shared__ int   hist[4096];                  // 16 KB; aliased as match bytes
    __shared__ int   suf[256];
    __shared__ float rs[512];
    __shared__ float rbx[512];
    __shared__ int   rn[512];
    __shared__ float gx0[MAXG], gy0[MAXG], gx1[MAXG], gy1[MAXG];
    __shared__ int   glab[MAXG], bp[MAXG];
    __shared__ int   f_bucket, f_above, sh_k, sh_last;
    __shared__ float sh_ce;
    unsigned char* smb = (unsigned char*)hist;    // apply phase only

    // stage keys (P % 4 == 0, 16B-aligned base)
    {
        const uint4* nk4 = (const uint4*)(g_negkey + b * P);
        const int nv = P >> 2;
        for (int i = tid; i < nv; i += NT) {
            uint4 v = __ldg(&nk4[i]);
            sk[i * 4 + 0] = v.x; sk[i * 4 + 1] = v.y;
            sk[i * 4 + 2] = v.z; sk[i * 4 + 3] = v.w;
        }
        for (int i = (nv << 2) + tid; i < P; i += NT) sk[i] = g_negkey[b * P + i];
    }
    // stage match bytes (b*P % 4 == 0 -> 4B loads)
    {
        const unsigned* mb4 = (const unsigned*)(g_mbyte + b * P);
        const int nv = P >> 2;
        for (int i = tid; i < nv; i += NT)
            ((unsigned*)smb)[i] = __ldg(&mb4[i]);
        for (int i = (nv << 2) + tid; i < P; i += NT) smb[i] = g_mbyte[b * P + i];
    }
    if (tid < G) {
        float4 gv = __ldg((const float4*)gt_boxes + b * G + tid);
        gx0[tid] = gv.x; gy0[tid] = gv.y; gx1[tid] = gv.z; gy1[tid] = gv.w;
        glab[tid] = gt_labels[b * G + tid];
        unsigned long long k = g_bestkey[b * MAXG + tid];
        bp[tid] = (int)(0xFFFFFFFFu - (unsigned)(k & 0xFFFFFFFFull));
        g_bestkey[b * MAXG + tid] = 0ull;         // reset for next replay
    }
    __syncthreads();

    // inject best-prior overrides (ascending g: last-GT-wins, matches .set)
    if (tid == 0) {
        for (int g = 0; g < G; g++)
            smb[bp[g]] = (unsigned char)(0x80 | g);
    }
    __syncthreads();

    // ---- apply: positives -> CE + box smooth-L1, zero their keys ----
    float ce = 0.0f, bxs = 0.0f;
    int np = 0;
    for (int p = tid; p < P; p += NT) {
        unsigned char mb = smb[p];
        if (mb & 0x80) {
            const int mg = mb & 15;
            np++;
            float bg = __uint_as_float(sk[p]);
            sk[p] = 0u;
            const float* rowp = logits + ((size_t)(b * P + p)) * C;
            float x0 = __ldg(rowp);
            float xl = __ldg(rowp + glab[mg]);
            ce += bg + x0 - xl;                    // = lse - x[lab] (1-ulp recomb)

            float4 pv = __ldg((const float4*)priors + p);
            float bx0 = gx0[mg], by0 = gy0[mg], bx1 = gx1[mg], by1 = gy1[mg];
            float t0 = ((bx0 + bx1) * 0.5f - pv.x) / (0.1f * pv.z);
            float t1 = ((by0 + by1) * 0.5f - pv.y) / (0.1f * pv.w);
            float t2 = logf((bx1 - bx0) / pv.z) / 0.2f;
            float t3 = logf((by1 - by0) / pv.w) / 0.2f;
            float4 br = __ldg((const float4*)box_reg + (b * P + p));
            float d0 = fabsf(br.x - t0), d1 = fabsf(br.y - t1);
            float d2 = fabsf(br.z - t2), d3 = fabsf(br.w - t3);
            bxs += (d0 < 1.0f) ? 0.5f * d0 * d0 : d0 - 0.5f;
            bxs += (d1 < 1.0f) ? 0.5f * d1 * d1 : d1 - 0.5f;
            bxs += (d2 < 1.0f) ? 0.5f * d2 * d2 : d2 - 0.5f;
            bxs += (d3 < 1.0f) ? 0.5f * d3 * d3 : d3 - 0.5f;
        }
    }
    rs[tid] = ce; rbx[tid] = bxs; rn[tid] = np;
    __syncthreads();
    for (int st = NT / 2; st > 0; st >>= 1) {
        if (tid < st) { rs[tid] += rs[tid + st]; rbx[tid] += rbx[tid + st]; rn[tid] += rn[tid + st]; }
        __syncthreads();
    }
    if (tid == 0) {
        int k = rn[0] * 3; if (k > P) k = P;
        sh_k = k; sh_ce = rs[0];
        g_batch_box[b] = rbx[0];
        g_batch_np[b]  = rn[0];
    }
    __syncthreads();
    int k = sh_k;

    // ---- exact top-k sum: 3-pass histogram select (12+12+8 bits) ----
    float cls = sh_ce;
    if (k > 0) {
        unsigned prefix = 0;
        const int shifts[3] = {20, 8, 0};
        const int bitsA[3]  = {12, 12, 8};
#pragma unroll
        for (int ps = 0; ps < 3; ps++) {
            const int shift = shifts[ps];
            const int nbits = bitsA[ps];
            const int nb = 1 << nbits;
            const unsigned himask = (unsigned)(~((1ull << (shift + nbits)) - 1ull));

            for (int i = tid; i < nb; i += NT) hist[i] = 0;
            __syncthreads();

            for (int p = tid; p < P; p += NT) {
                unsigned key = sk[p];
                if ((key & himask) == prefix)
                    atomicAdd(&hist[(key >> shift) & (nb - 1)], 1);
            }
            __syncthreads();

            const int cw = nb >> 8;
            int cs = 0;
            if (tid < 256) {
                for (int i = 0; i < cw; i++) cs += hist[tid * cw + i];
                suf[tid] = cs;
            }
            __syncthreads();
            for (int off = 1; off < 256; off <<= 1) {
                int v = 0;
                if (tid < 256) v = (tid + off < 256) ? suf[tid + off] : 0;
                __syncthreads();
                if (tid < 256) suf[tid] += v;
                __syncthreads();
            }
            if (tid < 256) {
                int running = suf[tid] - cs;                 // strictly above my chunk
                for (int i = cw - 1; i >= 0; i--) {
                    int c = hist[tid * cw + i];
                    if (c > 0 && running < k && running + c >= k) {
                        f_bucket = tid * cw + i;             // unique writer
                        f_above  = running;
                    }
                    running += c;
                }
            }
            __syncthreads();
            prefix |= ((unsigned)f_bucket) << shift;
            k -= f_above;
            __syncthreads();
        }

        float ss = 0.0f;
        for (int p = tid; p < P; p += NT) {
            unsigned key = sk[p];
            if (key > prefix) ss += __uint_as_float(key);
        }
        rs[tid] = ss;
        __syncthreads();
        for (int st = NT / 2; st > 0; st >>= 1) {
            if (tid < st) rs[tid] += rs[tid + st];
            __syncthreads();
        }
        cls += rs[0] + (float)k * __uint_as_float(prefix);   // residual ties
    }

    if (tid == 0) {
        g_batch_cls[b] = cls;
        __threadfence();
        int v = atomicAdd(&g_done, 1);
        sh_last = (v == B - 1) ? 1 : 0;
    }
    __syncthreads();

    // ---- last-finishing block: finalize ----
    if (sh_last) {
        float box = 0.0f, ctot = 0.0f; int npos = 0;
        for (int i = tid; i < B; i += NT) {
            box  += *(volatile float*)&g_batch_box[i];
            ctot += *(volatile float*)&g_batch_cls[i];
            npos += *(volatile int*)&g_batch_np[i];
        }
        rs[tid] = ctot; rbx[tid] = box; rn[tid] = npos;
        __syncthreads();
        for (int st = NT / 2; st > 0; st >>= 1) {
            if (tid < st) { rs[tid] += rs[tid + st]; rbx[tid] += rbx[tid + st]; rn[tid] += rn[tid + st]; }
            __syncthreads();
        }
        if (tid == 0) {
            float inv = 1.0f / (float)rn[0];
            out[0] = rbx[0] * inv;
            out[1] = rs[0] * inv;
            g_done = 0;                                      // self-reset for replay
        }
    }
}

// =====================================================================
extern "C" void kernel_launch(void* const* d_in, const int* in_sizes, int n_in,
                              void* d_out, int out_size)
{
    const float* priors = (const float*)d_in[0];
    const float* logits = (const float*)d_in[1];
    const float* boxreg = (const float*)d_in[2];
    const float* gtb    = (const float*)d_in[3];
    const int*   gtl    = (const int*)d_in[4];

    const int P = in_sizes[0] / 4;
    const int B = in_sizes[2] / (4 * P);
    const int C = in_sizes[1] / (B * P);
    const int G = in_sizes[4] / B;

    const int nTiles = (P + TILE - 1) / TILE;
    const int nblk   = (P + SM_ROWS - 1) / SM_ROWS;
    const int nMatch = B * nTiles;

    fused_ms<<<nMatch + B * nblk, 256>>>(logits, priors, gtb,
                                         P, C, G, nMatch, nTiles, nblk);

    apply_topk<<<B, 512>>>((float*)d_out, logits, priors, boxreg, gtb, gtl,
                           P, C, G, B);
}

// round 7
// speedup vs baseline: 1.1973x; 1.0625x over previous
#include <cuda_runtime.h>
#include <math.h>
#include <stdint.h>

#define MAXB    64
#define MAXP    8732
#define MAXBP   (MAXB * MAXP)
#define MAXG    16
#define TILE    256
#define SM_ROWS 64

// ---------------- scratch (static device globals; zero-initialized) -------------
__device__ unsigned      g_negkey[MAXBP];
__device__ unsigned char g_mbyte[MAXBP];                 // bit7 = pos, bits0-3 = argmax g
__device__ unsigned long long g_bestkey[MAXB * MAXG];    // zero-init; reset by K2
__device__ float g_batch_cls[MAXB];
__device__ float g_batch_box[MAXB];
__device__ int   g_batch_np[MAXB];
__device__ int   g_done;

// =====================================================================
// K1: heterogeneous kernel, match blocks interleaved 1-in-4 with
// softmax blocks so ALU-bound match hides under DRAM-bound softmax.
// =====================================================================
__global__ __launch_bounds__(256) void fused_ms(
    const float* __restrict__ logits,
    const float* __restrict__ priors,
    const float* __restrict__ gt_boxes,
    int P, int C, int G, int nMatch, int nTiles, int nblk)
{
    __shared__ float4 sbuf4[SM_ROWS * 81 / 4];    // softmax stage / match iou tile
    __shared__ float gx0[MAXG], gy0[MAXG], gx1[MAXG], gy1[MAXG], ga[MAXG];

    const int tid = threadIdx.x;
    const int bid = blockIdx.x;
    const bool isMatch = ((bid & 3) == 0) && ((bid >> 2) < nMatch);

    if (isMatch) {
        // ---------------- match role: 256 priors per block ----------------
        const int mi = bid >> 2;
        const int b = mi / nTiles;
        const int t = mi % nTiles;
        unsigned* siou = (unsigned*)sbuf4;        // [16][TILE] iou bits

        if (tid < G) {
            float4 gv = __ldg((const float4*)gt_boxes + b * G + tid);
            gx0[tid] = gv.x; gy0[tid] = gv.y; gx1[tid] = gv.z; gy1[tid] = gv.w;
            ga[tid]  = (gv.z - gv.x) * (gv.w - gv.y);
        }
        __syncthreads();

        const int p0 = t * TILE;
        const int p  = p0 + tid;

        if (p < P) {
            float4 pv = __ldg((const float4*)priors + p);
            float px0 = pv.x - 0.5f * pv.z, py0 = pv.y - 0.5f * pv.w;
            float px1 = pv.x + 0.5f * pv.z, py1 = pv.y + 0.5f * pv.w;
            float parea = (px1 - px0) * (py1 - py0);

            float mval = -1.0f; int mg = 0;
#pragma unroll
            for (int g = 0; g < MAXG; g++) {
                if (g >= G) break;
                float ix0 = fmaxf(gx0[g], px0), iy0 = fmaxf(gy0[g], py0);
                float ix1 = fminf(gx1[g], px1), iy1 = fminf(gy1[g], py1);
                float iw = fmaxf(ix1 - ix0, 0.0f), ih = fmaxf(iy1 - iy0, 0.0f);
                float inter = iw * ih;
                float iou = inter / (ga[g] + parea - inter); // IEEE div (matches ref)
                if (iou > mval) { mval = iou; mg = g; }      // first-g tie-break
                siou[g * TILE + tid] = __float_as_uint(iou); // iou>=0 => ordered bits
            }
            g_mbyte[b * P + p] =
                (unsigned char)(mg | ((mval >= 0.5f) ? 0x80 : 0));
        } else {
#pragma unroll
            for (int g = 0; g < MAXG; g++) {
                if (g >= G) break;
                siou[g * TILE + tid] = 0u;
            }
        }
        __syncthreads();

        const int warp = tid >> 5, lane = tid & 31;
#pragma unroll
        for (int gg = warp; gg < MAXG; gg += 8) {
            if (gg >= G) break;
            unsigned long long best = 0ull;
#pragma unroll
            for (int i = 0; i < TILE / 32; i++) {
                const int c = lane + 32 * i;
                unsigned bits = siou[gg * TILE + c];
                unsigned long long key =
                    ((unsigned long long)bits << 32) |
                    (unsigned long long)(0xFFFFFFFFu - (unsigned)(p0 + c));
                if (key > best) best = key;                  // lower p wins ties
            }
#pragma unroll
            for (int o = 16; o > 0; o >>= 1) {
                unsigned long long other = __shfl_down_sync(0xffffffffu, best, o);
                if (other > best) best = other;
            }
            if (lane == 0) atomicMax(&g_bestkey[b * MAXG + gg], best);
        }
    } else {
        // ---------------- softmax role: 64 rows per block ----------------
        const int nm_before = min((bid + 3) >> 2, nMatch);
        const int r  = bid - nm_before;
        const int b  = r / nblk;
        const int bx = r % nblk;
        const int r0 = bx * SM_ROWS;
        const int R  = min(SM_ROWS, P - r0);

        const float* base = logits + ((size_t)b * P + r0) * C;
        const int nflt = R * C;
        const int nvec = nflt >> 2;
        const float4* b4 = (const float4*)base;
        for (int i = tid; i < nvec; i += 256)
            sbuf4[i] = __ldg(&b4[i]);                        // STS.128
        float* sbuf = (float*)sbuf4;
        for (int i = (nvec << 2) + tid; i < nflt; i += 256) sbuf[i] = __ldg(&base[i]);
        __syncthreads();

        const int warp = tid >> 5, lane = tid & 31;
#pragma unroll
        for (int j = 0; j < SM_ROWS / 8; j++) {
            const int row = warp + j * 8;
            if (row >= R) break;
            const float* rp = sbuf + row * 81;
            float sum = 0.0f;
            if (lane      < C) sum += __expf(rp[lane]);
            if (lane + 32 < C) sum += __expf(rp[lane + 32]);
            if (lane + 64 < C) sum += __expf(rp[lane + 64]);
#pragma unroll
            for (int o = 16; o > 0; o >>= 1)
                sum += __shfl_xor_sync(0xffffffffu, sum, o);
            if (lane == 0) {
                float lse = __logf(sum);
                g_negkey[b * P + r0 + row] =
                    __float_as_uint(fmaxf(lse - rp[0], 0.0f));   // bg_loss >= 0
            }
        }
    }
}

// =====================================================================
// K2: per-batch apply + exact top-k + finalize.  One block per batch,
// 1024 threads.  Warp-aggregated histogram atomics (keys cluster!),
// shuffle reductions, 3-barrier suffix scan.
// =====================================================================
__global__ __launch_bounds__(1024) void apply_topk(
    float* __restrict__ out,
    const float* __restrict__ logits,
    const float* __restrict__ priors,
    const float* __restrict__ box_reg,
    const float* __restrict__ gt_boxes,
    const int*   __restrict__ gt_labels,
    int P, int C, int G, int B)
{
    const int b = blockIdx.x;
    const int tid = threadIdx.x;
    const int NT = 1024;
    const int lane = tid & 31, warp = tid >> 5;

    __shared__ unsigned sk[MAXP];                 // 34.9 KB keys
    __shared__ int   hist[4096];                  // aliased as match bytes
    __shared__ int   suf[256];
    __shared__ float wsf[32], wsf2[32];
    __shared__ int   wsi[32];
    __shared__ float gx0[MAXG], gy0[MAXG], gx1[MAXG], gy1[MAXG];
    __shared__ int   glab[MAXG], bp[MAXG];
    __shared__ int   f_bucket, f_above, sh_k, sh_last, sh_np;
    __shared__ float sh_ce, sh_box;
    unsigned char* smb = (unsigned char*)hist;    // apply phase only

    // stage keys + match bytes
    {
        const uint4* nk4 = (const uint4*)(g_negkey + b * P);
        const int nv = P >> 2;
        for (int i = tid; i < nv; i += NT) {
            uint4 v = __ldg(&nk4[i]);
            sk[i * 4 + 0] = v.x; sk[i * 4 + 1] = v.y;
            sk[i * 4 + 2] = v.z; sk[i * 4 + 3] = v.w;
        }
        for (int i = (nv << 2) + tid; i < P; i += NT) sk[i] = g_negkey[b * P + i];
        const unsigned* mb4 = (const unsigned*)(g_mbyte + b * P);
        for (int i = tid; i < nv; i += NT) ((unsigned*)smb)[i] = __ldg(&mb4[i]);
        for (int i = (nv << 2) + tid; i < P; i += NT) smb[i] = g_mbyte[b * P + i];
    }
    if (tid < G) {
        float4 gv = __ldg((const float4*)gt_boxes + b * G + tid);
        gx0[tid] = gv.x; gy0[tid] = gv.y; gx1[tid] = gv.z; gy1[tid] = gv.w;
        glab[tid] = gt_labels[b * G + tid];
        unsigned long long k = g_bestkey[b * MAXG + tid];
        bp[tid] = (int)(0xFFFFFFFFu - (unsigned)(k & 0xFFFFFFFFull));
        g_bestkey[b * MAXG + tid] = 0ull;         // reset for next replay
    }
    __syncthreads();

    // inject best-prior overrides (ascending g: last-GT-wins, matches .set)
    if (tid == 0) {
        for (int g = 0; g < G; g++)
            smb[bp[g]] = (unsigned char)(0x80 | g);
    }
    __syncthreads();

    // ---- apply: positives -> CE + box smooth-L1, zero their keys ----
    float ce = 0.0f, bxs = 0.0f;
    int np = 0;
    for (int p = tid; p < P; p += NT) {
        unsigned char mb = smb[p];
        if (mb & 0x80) {
            const int mg = mb & 15;
            np++;
            float bg = __uint_as_float(sk[p]);
            sk[p] = 0u;
            const float* rowp = logits + ((size_t)(b * P + p)) * C;
            float x0 = __ldg(rowp);
            float xl = __ldg(rowp + glab[mg]);
            ce += bg + x0 - xl;                    // = lse - x[lab]

            float4 pv = __ldg((const float4*)priors + p);
            float bx0 = gx0[mg], by0 = gy0[mg], bx1 = gx1[mg], by1 = gy1[mg];
            float t0 = ((bx0 + bx1) * 0.5f - pv.x) / (0.1f * pv.z);
            float t1 = ((by0 + by1) * 0.5f - pv.y) / (0.1f * pv.w);
            float t2 = logf((bx1 - bx0) / pv.z) / 0.2f;
            float t3 = logf((by1 - by0) / pv.w) / 0.2f;
            float4 br = __ldg((const float4*)box_reg + (b * P + p));
            float d0 = fabsf(br.x - t0), d1 = fabsf(br.y - t1);
            float d2 = fabsf(br.z - t2), d3 = fabsf(br.w - t3);
            bxs += (d0 < 1.0f) ? 0.5f * d0 * d0 : d0 - 0.5f;
            bxs += (d1 < 1.0f) ? 0.5f * d1 * d1 : d1 - 0.5f;
            bxs += (d2 < 1.0f) ? 0.5f * d2 * d2 : d2 - 0.5f;
            bxs += (d3 < 1.0f) ? 0.5f * d3 * d3 : d3 - 0.5f;
        }
    }
    // shuffle block reduction (ce, box, np)
#pragma unroll
    for (int o = 16; o > 0; o >>= 1) {
        ce  += __shfl_down_sync(0xffffffffu, ce, o);
        bxs += __shfl_down_sync(0xffffffffu, bxs, o);
        np  += __shfl_down_sync(0xffffffffu, np, o);
    }
    if (lane == 0) { wsf[warp] = ce; wsf2[warp] = bxs; wsi[warp] = np; }
    __syncthreads();
    if (warp == 0) {
        float c2 = wsf[lane], b2 = wsf2[lane];
        int n2 = wsi[lane];
#pragma unroll
        for (int o = 16; o > 0; o >>= 1) {
            c2 += __shfl_down_sync(0xffffffffu, c2, o);
            b2 += __shfl_down_sync(0xffffffffu, b2, o);
            n2 += __shfl_down_sync(0xffffffffu, n2, o);
        }
        if (lane == 0) {
            int k = n2 * 3; if (k > P) k = P;
            sh_k = k; sh_ce = c2; sh_box = b2; sh_np = n2;
            g_batch_box[b] = b2;
            g_batch_np[b]  = n2;
        }
    }
    __syncthreads();
    int k = sh_k;

    // ---- exact top-k sum: 3-pass histogram select, warp-aggregated ----
    float cls = sh_ce;
    if (k > 0) {
        unsigned prefix = 0;
        const int shifts[3] = {20, 8, 0};
        const int bitsA[3]  = {12, 12, 8};
        const int iters = (P + NT - 1) / NT;
#pragma unroll
        for (int ps = 0; ps < 3; ps++) {
            const int shift = shifts[ps];
            const int nbits = bitsA[ps];
            const int nb = 1 << nbits;
            const unsigned himask = (unsigned)(~((1ull << (shift + nbits)) - 1ull));

            for (int i = tid; i < nb; i += NT) hist[i] = 0;
            __syncthreads();

            for (int it = 0; it < iters; it++) {
                const int p = tid + it * NT;
                unsigned key = (p < P) ? sk[p] : 0u;
                const bool act = (p < P) && ((key & himask) == prefix);
                unsigned bkt = act ? ((key >> shift) & (nb - 1)) : 0xFFFFFFFFu;
                unsigned mm = __match_any_sync(0xffffffffu, bkt);
                if (act && ((int)(__ffs(mm) - 1) == lane))
                    atomicAdd(&hist[bkt], __popc(mm));
            }
            __syncthreads();

            // suffix scan over 256 chunk sums (warp shuffles, 3 barriers)
            const int cw = nb >> 8;
            int cs = 0;
            if (tid < 256)
                for (int i = 0; i < cw; i++) cs += hist[tid * cw + i];
            int v = cs;
#pragma unroll
            for (int o = 1; o < 32; o <<= 1) {
                int u = __shfl_down_sync(0xffffffffu, v, o);
                if (lane + o < 32) v += u;
            }
            if (tid < 256 && lane == 0) wsi[warp] = v;   // warp totals (warps 0-7)
            __syncthreads();
            if (tid < 256) {
                int off = 0;
                for (int w2 = warp + 1; w2 < 8; w2++) off += wsi[w2];
                suf[tid] = v + off;                      // inclusive suffix
            }
            __syncthreads();
            if (tid < 256) {
                int running = suf[tid] - cs;             // strictly above my chunk
                for (int i = cw - 1; i >= 0; i--) {
                    int c = hist[tid * cw + i];
                    if (c > 0 && running < k && running + c >= k) {
                        f_bucket = tid * cw + i;         // unique writer
                        f_above  = running;
                    }
                    running += c;
                }
            }
            __syncthreads();
            prefix |= ((unsigned)f_bucket) << shift;
            k -= f_above;
            __syncthreads();
        }

        float ss = 0.0f;
        for (int p = tid; p < P; p += NT) {
            unsigned key = sk[p];
            if (key > prefix) ss += __uint_as_float(key);
        }
#pragma unroll
        for (int o = 16; o > 0; o >>= 1) ss += __shfl_down_sync(0xffffffffu, ss, o);
        if (lane == 0) wsf[warp] = ss;
        __syncthreads();
        if (warp == 0) {
            float s2 = wsf[lane];
#pragma unroll
            for (int o = 16; o > 0; o >>= 1) s2 += __shfl_down_sync(0xffffffffu, s2, o);
            if (lane == 0) wsf[0] = s2;
        }
        __syncthreads();
        cls += wsf[0] + (float)k * __uint_as_float(prefix);  // residual ties
    }

    if (tid == 0) {
        g_batch_cls[b] = cls;
        __threadfence();
        int v = atomicAdd(&g_done, 1);
        sh_last = (v == B - 1) ? 1 : 0;
    }
    __syncthreads();

    // ---- last-finishing block: finalize ----
    if (sh_last) {
        float box = 0.0f, ctot = 0.0f; int npos = 0;
        for (int i = tid; i < B; i += NT) {
            box  += *(volatile float*)&g_batch_box[i];
            ctot += *(volatile float*)&g_batch_cls[i];
            npos += *(volatile int*)&g_batch_np[i];
        }
#pragma unroll
        for (int o = 16; o > 0; o >>= 1) {
            box  += __shfl_down_sync(0xffffffffu, box, o);
            ctot += __shfl_down_sync(0xffffffffu, ctot, o);
            npos += __shfl_down_sync(0xffffffffu, npos, o);
        }
        if (lane == 0) { wsf[warp] = box; wsf2[warp] = ctot; wsi[warp] = npos; }
        __syncthreads();
        if (warp == 0) {
            float b2 = wsf[lane], c2 = wsf2[lane];
            int n2 = wsi[lane];
#pragma unroll
            for (int o = 16; o > 0; o >>= 1) {
                b2 += __shfl_down_sync(0xffffffffu, b2, o);
                c2 += __shfl_down_sync(0xffffffffu, c2, o);
                n2 += __shfl_down_sync(0xffffffffu, n2, o);
            }
            if (lane == 0) {
                float inv = 1.0f / (float)n2;
                out[0] = b2 * inv;
                out[1] = c2 * inv;
                g_done = 0;                              // self-reset for replay
            }
        }
    }
}

// =====================================================================
extern "C" void kernel_launch(void* const* d_in, const int* in_sizes, int n_in,
                              void* d_out, int out_size)
{
    const float* priors = (const float*)d_in[0];
    const float* logits = (const float*)d_in[1];
    const float* boxreg = (const float*)d_in[2];
    const float* gtb    = (const float*)d_in[3];
    const int*   gtl    = (const int*)d_in[4];

    const int P = in_sizes[0] / 4;
    const int B = in_sizes[2] / (4 * P);
    const int C = in_sizes[1] / (B * P);
    const int G = in_sizes[4] / B;

    const int nTiles = (P + TILE - 1) / TILE;
    const int nblk   = (P + SM_ROWS - 1) / SM_ROWS;
    const int nMatch = B * nTiles;

    fused_ms<<<nMatch + B * nblk, 256>>>(logits, priors, gtb,
                                         P, C, G, nMatch, nTiles, nblk);

    apply_topk<<<B, 1024>>>((float*)d_out, logits, priors, boxreg, gtb, gtl,
                            P, C, G, B);
}

// round 8
// speedup vs baseline: 1.2035x; 1.0052x over previous
#include <cuda_runtime.h>
#include <math.h>
#include <stdint.h>

#define MAXB    64
#define MAXP    8732
#define MAXBP   (MAXB * MAXP)
#define MAXG    16
#define TILE    256
#define SM_ROWS 64

// ---------------- scratch (static device globals; zero-initialized) -------------
__device__ unsigned      g_negkey[MAXBP];
__device__ unsigned char g_mbyte[MAXBP];                 // bit7 = pos, bits0-3 = argmax g
__device__ unsigned long long g_bestkey[MAXB * MAXG];    // zero-init; reset by K2
__device__ float g_batch_cls[MAXB];
__device__ float g_batch_box[MAXB];
__device__ int   g_batch_np[MAXB];
__device__ int   g_done;

// =====================================================================
// K1: heterogeneous kernel, match blocks interleaved 1-in-4 with
// softmax blocks.  Softmax staging uses explicit 6-deep batched loads
// (MLP=6) so the logits stream is bandwidth- not latency-bound.
// =====================================================================
__global__ __launch_bounds__(256) void fused_ms(
    const float* __restrict__ logits,
    const float* __restrict__ priors,
    const float* __restrict__ gt_boxes,
    int P, int C, int G, int nMatch, int nTiles, int nblk)
{
    __shared__ float4 sbuf4[SM_ROWS * 81 / 4];    // softmax stage / match iou tile
    __shared__ float gx0[MAXG], gy0[MAXG], gx1[MAXG], gy1[MAXG], ga[MAXG];

    const int tid = threadIdx.x;
    const int bid = blockIdx.x;
    const bool isMatch = ((bid & 3) == 0) && ((bid >> 2) < nMatch);

    if (isMatch) {
        // ---------------- match role: 256 priors per block ----------------
        const int mi = bid >> 2;
        const int b = mi / nTiles;
        const int t = mi % nTiles;
        unsigned* siou = (unsigned*)sbuf4;        // [16][TILE] iou bits

        if (tid < G) {
            float4 gv = __ldg((const float4*)gt_boxes + b * G + tid);
            gx0[tid] = gv.x; gy0[tid] = gv.y; gx1[tid] = gv.z; gy1[tid] = gv.w;
            ga[tid]  = (gv.z - gv.x) * (gv.w - gv.y);
        }
        __syncthreads();

        const int p0 = t * TILE;
        const int p  = p0 + tid;

        if (p < P) {
            float4 pv = __ldg((const float4*)priors + p);
            float px0 = pv.x - 0.5f * pv.z, py0 = pv.y - 0.5f * pv.w;
            float px1 = pv.x + 0.5f * pv.z, py1 = pv.y + 0.5f * pv.w;
            float parea = (px1 - px0) * (py1 - py0);

            float mval = -1.0f; int mg = 0;
#pragma unroll
            for (int g = 0; g < MAXG; g++) {
                if (g >= G) break;
                float ix0 = fmaxf(gx0[g], px0), iy0 = fmaxf(gy0[g], py0);
                float ix1 = fminf(gx1[g], px1), iy1 = fminf(gy1[g], py1);
                float iw = fmaxf(ix1 - ix0, 0.0f), ih = fmaxf(iy1 - iy0, 0.0f);
                float inter = iw * ih;
                float iou = inter / (ga[g] + parea - inter); // IEEE div (matches ref)
                if (iou > mval) { mval = iou; mg = g; }      // first-g tie-break
                siou[g * TILE + tid] = __float_as_uint(iou); // iou>=0 => ordered bits
            }
            g_mbyte[b * P + p] =
                (unsigned char)(mg | ((mval >= 0.5f) ? 0x80 : 0));
        } else {
#pragma unroll
            for (int g = 0; g < MAXG; g++) {
                if (g >= G) break;
                siou[g * TILE + tid] = 0u;
            }
        }
        __syncthreads();

        const int warp = tid >> 5, lane = tid & 31;
#pragma unroll
        for (int gg = warp; gg < MAXG; gg += 8) {
            if (gg >= G) break;
            unsigned long long best = 0ull;
#pragma unroll
            for (int i = 0; i < TILE / 32; i++) {
                const int c = lane + 32 * i;
                unsigned bits = siou[gg * TILE + c];
                unsigned long long key =
                    ((unsigned long long)bits << 32) |
                    (unsigned long long)(0xFFFFFFFFu - (unsigned)(p0 + c));
                if (key > best) best = key;                  // lower p wins ties
            }
#pragma unroll
            for (int o = 16; o > 0; o >>= 1) {
                unsigned long long other = __shfl_down_sync(0xffffffffu, best, o);
                if (other > best) best = other;
            }
            if (lane == 0) atomicMax(&g_bestkey[b * MAXG + gg], best);
        }
    } else {
        // ---------------- softmax role: 64 rows per block ----------------
        const int nm_before = min((bid + 3) >> 2, nMatch);
        const int r  = bid - nm_before;
        const int b  = r / nblk;
        const int bx = r % nblk;
        const int r0 = bx * SM_ROWS;
        const int R  = min(SM_ROWS, P - r0);

        const float* base = logits + ((size_t)b * P + r0) * C;
        const int nflt = R * C;
        const int nvec = nflt >> 2;
        const float4* b4 = (const float4*)base;

        if (nvec == (SM_ROWS * 81) / 4) {
            // full tile: 1296 float4 / 256 threads = 5 + 16-thread remainder.
            // batched independent loads (MLP=6), then stores.
            float4 v0 = __ldg(&b4[tid]);
            float4 v1 = __ldg(&b4[tid + 256]);
            float4 v2 = __ldg(&b4[tid + 512]);
            float4 v3 = __ldg(&b4[tid + 768]);
            float4 v4 = __ldg(&b4[tid + 1024]);
            float4 v5;
            const bool g5 = tid < (SM_ROWS * 81) / 4 - 1280;
            if (g5) v5 = __ldg(&b4[tid + 1280]);
            sbuf4[tid]        = v0;
            sbuf4[tid + 256]  = v1;
            sbuf4[tid + 512]  = v2;
            sbuf4[tid + 768]  = v3;
            sbuf4[tid + 1024] = v4;
            if (g5) sbuf4[tid + 1280] = v5;
        } else {
            float* sbuf = (float*)sbuf4;
            for (int i = tid; i < nvec; i += 256) sbuf4[i] = __ldg(&b4[i]);
            for (int i = (nvec << 2) + tid; i < nflt; i += 256)
                sbuf[i] = __ldg(&base[i]);
        }
        __syncthreads();

        const float* sbuf = (const float*)sbuf4;
        const int warp = tid >> 5, lane = tid & 31;
#pragma unroll
        for (int j = 0; j < SM_ROWS / 8; j++) {
            const int row = warp + j * 8;
            if (row >= R) break;
            const float* rp = sbuf + row * 81;
            float sum = 0.0f;
            if (lane      < C) sum += __expf(rp[lane]);
            if (lane + 32 < C) sum += __expf(rp[lane + 32]);
            if (lane + 64 < C) sum += __expf(rp[lane + 64]);
#pragma unroll
            for (int o = 16; o > 0; o >>= 1)
                sum += __shfl_xor_sync(0xffffffffu, sum, o);
            if (lane == 0) {
                float lse = __logf(sum);
                g_negkey[b * P + r0 + row] =
                    __float_as_uint(fmaxf(lse - rp[0], 0.0f));   // bg_loss >= 0
            }
        }
    }
}

// =====================================================================
// K2: per-batch apply + exact top-k + finalize.  One block per batch,
// 1024 threads.  Batched staging (MLP=3), word-wise positive scan,
// warp-aggregated histogram atomics.
// =====================================================================
__global__ __launch_bounds__(1024) void apply_topk(
    float* __restrict__ out,
    const float* __restrict__ logits,
    const float* __restrict__ priors,
    const float* __restrict__ box_reg,
    const float* __restrict__ gt_boxes,
    const int*   __restrict__ gt_labels,
    int P, int C, int G, int B)
{
    const int b = blockIdx.x;
    const int tid = threadIdx.x;
    const int NT = 1024;
    const int lane = tid & 31, warp = tid >> 5;

    __shared__ unsigned sk[MAXP];                 // 34.9 KB keys
    __shared__ int   hist[4096];                  // aliased as match bytes
    __shared__ int   suf[256];
    __shared__ float wsf[32], wsf2[32];
    __shared__ int   wsi[32];
    __shared__ float gx0[MAXG], gy0[MAXG], gx1[MAXG], gy1[MAXG];
    __shared__ int   glab[MAXG], bp[MAXG];
    __shared__ int   f_bucket, f_above, sh_k, sh_last;
    __shared__ float sh_ce;
    unsigned char* smb = (unsigned char*)hist;    // apply phase only

    // stage keys + match bytes, batched loads (MLP=3 each)
    {
        const int nv = P >> 2;                    // P % 4 == 0
        const uint4* nk4 = (const uint4*)(g_negkey + b * P);
        const unsigned* mb4 = (const unsigned*)(g_mbyte + b * P);
        uint4 kv[3]; unsigned mv[3]; bool gd[3];
#pragma unroll
        for (int kk = 0; kk < 3; kk++) {
            const int i = tid + kk * NT;
            gd[kk] = i < nv;
            if (gd[kk]) { kv[kk] = __ldg(&nk4[i]); mv[kk] = __ldg(&mb4[i]); }
        }
#pragma unroll
        for (int kk = 0; kk < 3; kk++) {
            const int i = tid + kk * NT;
            if (gd[kk]) {
                sk[i * 4 + 0] = kv[kk].x; sk[i * 4 + 1] = kv[kk].y;
                sk[i * 4 + 2] = kv[kk].z; sk[i * 4 + 3] = kv[kk].w;
                ((unsigned*)smb)[i] = mv[kk];
            }
        }
        for (int i = tid + 3 * NT; i < nv; i += NT) {   // safety tail
            uint4 v = __ldg(&nk4[i]);
            sk[i * 4 + 0] = v.x; sk[i * 4 + 1] = v.y;
            sk[i * 4 + 2] = v.z; sk[i * 4 + 3] = v.w;
            ((unsigned*)smb)[i] = __ldg(&mb4[i]);
        }
    }
    if (tid < G) {
        float4 gv = __ldg((const float4*)gt_boxes + b * G + tid);
        gx0[tid] = gv.x; gy0[tid] = gv.y; gx1[tid] = gv.z; gy1[tid] = gv.w;
        glab[tid] = gt_labels[b * G + tid];
        unsigned long long k = g_bestkey[b * MAXG + tid];
        bp[tid] = (int)(0xFFFFFFFFu - (unsigned)(k & 0xFFFFFFFFull));
        g_bestkey[b * MAXG + tid] = 0ull;         // reset for next replay
    }
    __syncthreads();

    // inject best-prior overrides (ascending g: last-GT-wins, matches .set)
    if (tid == 0) {
        for (int g = 0; g < G; g++)
            smb[bp[g]] = (unsigned char)(0x80 | g);
    }
    __syncthreads();

    // ---- apply: word-wise scan, positives -> CE + box smooth-L1 ----
    float ce = 0.0f, bxs = 0.0f;
    int np = 0;
    {
        const int nwords = P >> 2;
        for (int i = tid; i < nwords; i += NT) {
            unsigned w4 = ((const unsigned*)smb)[i];
            if (w4 & 0x80808080u) {
#pragma unroll
                for (int j = 0; j < 4; j++) {
                    if ((w4 >> (8 * j + 7)) & 1u) {
                        const int p = i * 4 + j;
                        const int mg = (w4 >> (8 * j)) & 15;
                        np++;
                        float bg = __uint_as_float(sk[p]);
                        sk[p] = 0u;
                        const float* rowp = logits + ((size_t)(b * P + p)) * C;
                        float x0 = __ldg(rowp);
                        float xl = __ldg(rowp + glab[mg]);
                        ce += bg + x0 - xl;                // = lse - x[lab]

                        float4 pv = __ldg((const float4*)priors + p);
                        float bx0 = gx0[mg], by0 = gy0[mg];
                        float bx1 = gx1[mg], by1 = gy1[mg];
                        float t0 = ((bx0 + bx1) * 0.5f - pv.x) / (0.1f * pv.z);
                        float t1 = ((by0 + by1) * 0.5f - pv.y) / (0.1f * pv.w);
                        float t2 = __logf((bx1 - bx0) / pv.z) / 0.2f;
                        float t3 = __logf((by1 - by0) / pv.w) / 0.2f;
                        float4 br = __ldg((const float4*)box_reg + (b * P + p));
                        float d0 = fabsf(br.x - t0), d1 = fabsf(br.y - t1);
                        float d2 = fabsf(br.z - t2), d3 = fabsf(br.w - t3);
                        bxs += (d0 < 1.0f) ? 0.5f * d0 * d0 : d0 - 0.5f;
                        bxs += (d1 < 1.0f) ? 0.5f * d1 * d1 : d1 - 0.5f;
                        bxs += (d2 < 1.0f) ? 0.5f * d2 * d2 : d2 - 0.5f;
                        bxs += (d3 < 1.0f) ? 0.5f * d3 * d3 : d3 - 0.5f;
                    }
                }
            }
        }
    }
    // shuffle block reduction (ce, box, np)
#pragma unroll
    for (int o = 16; o > 0; o >>= 1) {
        ce  += __shfl_down_sync(0xffffffffu, ce, o);
        bxs += __shfl_down_sync(0xffffffffu, bxs, o);
        np  += __shfl_down_sync(0xffffffffu, np, o);
    }
    if (lane == 0) { wsf[warp] = ce; wsf2[warp] = bxs; wsi[warp] = np; }
    __syncthreads();
    if (warp == 0) {
        float c2 = wsf[lane], b2 = wsf2[lane];
        int n2 = wsi[lane];
#pragma unroll
        for (int o = 16; o > 0; o >>= 1) {
            c2 += __shfl_down_sync(0xffffffffu, c2, o);
            b2 += __shfl_down_sync(0xffffffffu, b2, o);
            n2 += __shfl_down_sync(0xffffffffu, n2, o);
        }
        if (lane == 0) {
            int k = n2 * 3; if (k > P) k = P;
            sh_k = k; sh_ce = c2;
            g_batch_box[b] = b2;
            g_batch_np[b]  = n2;
        }
    }
    __syncthreads();
    int k = sh_k;

    // ---- exact top-k sum: 3-pass histogram select, warp-aggregated ----
    float cls = sh_ce;
    if (k > 0) {
        unsigned prefix = 0;
        const int shifts[3] = {20, 8, 0};
        const int bitsA[3]  = {12, 12, 8};
        const int iters = (P + NT - 1) / NT;
#pragma unroll
        for (int ps = 0; ps < 3; ps++) {
            const int shift = shifts[ps];
            const int nbits = bitsA[ps];
            const int nb = 1 << nbits;
            const unsigned himask = (unsigned)(~((1ull << (shift + nbits)) - 1ull));

            for (int i = tid; i < nb; i += NT) hist[i] = 0;
            __syncthreads();

            for (int it = 0; it < iters; it++) {
                const int p = tid + it * NT;
                unsigned key = (p < P) ? sk[p] : 0u;
                const bool act = (p < P) && ((key & himask) == prefix);
                unsigned bkt = act ? ((key >> shift) & (nb - 1)) : 0xFFFFFFFFu;
                unsigned mm = __match_any_sync(0xffffffffu, bkt);
                if (act && ((int)(__ffs(mm) - 1) == lane))
                    atomicAdd(&hist[bkt], __popc(mm));
            }
            __syncthreads();

            // suffix scan over 256 chunk sums (warp shuffles)
            const int cw = nb >> 8;
            int cs = 0;
            if (tid < 256)
                for (int i = 0; i < cw; i++) cs += hist[tid * cw + i];
            int v = cs;
#pragma unroll
            for (int o = 1; o < 32; o <<= 1) {
                int u = __shfl_down_sync(0xffffffffu, v, o);
                if (lane + o < 32) v += u;
            }
            if (tid < 256 && lane == 0) wsi[warp] = v;   // warp totals (warps 0-7)
            __syncthreads();
            if (tid < 256) {
                int off = 0;
                for (int w2 = warp + 1; w2 < 8; w2++) off += wsi[w2];
                suf[tid] = v + off;                      // inclusive suffix
            }
            __syncthreads();
            if (tid < 256) {
                int running = suf[tid] - cs;             // strictly above my chunk
                for (int i = cw - 1; i >= 0; i--) {
                    int c = hist[tid * cw + i];
                    if (c > 0 && running < k && running + c >= k) {
                        f_bucket = tid * cw + i;         // unique writer
                        f_above  = running;
                    }
                    running += c;
                }
            }
            __syncthreads();
            prefix |= ((unsigned)f_bucket) << shift;
            k -= f_above;
            __syncthreads();
        }

        float ss = 0.0f;
        for (int p = tid; p < P; p += NT) {
            unsigned key = sk[p];
            if (key > prefix) ss += __uint_as_float(key);
        }
#pragma unroll
        for (int o = 16; o > 0; o >>= 1) ss += __shfl_down_sync(0xffffffffu, ss, o);
        if (lane == 0) wsf[warp] = ss;
        __syncthreads();
        if (warp == 0) {
            float s2 = wsf[lane];
#pragma unroll
            for (int o = 16; o > 0; o >>= 1) s2 += __shfl_down_sync(0xffffffffu, s2, o);
            if (lane == 0) wsf[0] = s2;
        }
        __syncthreads();
        cls += wsf[0] + (float)k * __uint_as_float(prefix);  // residual ties
    }

    if (tid == 0) {
        g_batch_cls[b] = cls;
        __threadfence();
        int v = atomicAdd(&g_done, 1);
        sh_last = (v == B - 1) ? 1 : 0;
    }
    __syncthreads();

    // ---- last-finishing block: finalize ----
    if (sh_last) {
        float box = 0.0f, ctot = 0.0f; int npos = 0;
        for (int i = tid; i < B; i += NT) {
            box  += *(volatile float*)&g_batch_box[i];
            ctot += *(volatile float*)&g_batch_cls[i];
            npos += *(volatile int*)&g_batch_np[i];
        }
#pragma unroll
        for (int o = 16; o > 0; o >>= 1) {
            box  += __shfl_down_sync(0xffffffffu, box, o);
            ctot += __shfl_down_sync(0xffffffffu, ctot, o);
            npos += __shfl_down_sync(0xffffffffu, npos, o);
        }
        if (lane == 0) { wsf[warp] = box; wsf2[warp] = ctot; wsi[warp] = npos; }
        __syncthreads();
        if (warp == 0) {
            float b2 = wsf[lane], c2 = wsf2[lane];
            int n2 = wsi[lane];
#pragma unroll
            for (int o = 16; o > 0; o >>= 1) {
                b2 += __shfl_down_sync(0xffffffffu, b2, o);
                c2 += __shfl_down_sync(0xffffffffu, c2, o);
                n2 += __shfl_down_sync(0xffffffffu, n2, o);
            }
            if (lane == 0) {
                float inv = 1.0f / (float)n2;
                out[0] = b2 * inv;
                out[1] = c2 * inv;
                g_done = 0;                              // self-reset for replay
            }
        }
    }
}

// =====================================================================
extern "C" void kernel_launch(void* const* d_in, const int* in_sizes, int n_in,
                              void* d_out, int out_size)
{
    const float* priors = (const float*)d_in[0];
    const float* logits = (const float*)d_in[1];
    const float* boxreg = (const float*)d_in[2];
    const float* gtb    = (const float*)d_in[3];
    const int*   gtl    = (const int*)d_in[4];

    const int P = in_sizes[0] / 4;
    const int B = in_sizes[2] / (4 * P);
    const int C = in_sizes[1] / (B * P);
    const int G = in_sizes[4] / B;

    const int nTiles = (P + TILE - 1) / TILE;
    const int nblk   = (P + SM_ROWS - 1) / SM_ROWS;
    const int nMatch = B * nTiles;

    fused_ms<<<nMatch + B * nblk, 256>>>(logits, priors, gtb,
                                         P, C, G, nMatch, nTiles, nblk);

    apply_topk<<<B, 1024>>>((float*)d_out, logits, priors, boxreg, gtb, gtl,
                            P, C, G, B);
}